// round 4
// baseline (speedup 1.0000x reference)
#include <cuda_runtime.h>
#include <cstdint>

// Problem constants
#define NFFT 8192
#define HALF 4096
#define LOGN 13
#define GD   128
#define BC   16
#define KC   4
#define MC   4
#define PC   6
#define BKC  (BC*KC)   // 64
#define THREADS_FFT 1024

// Scratch (device globals — no allocation allowed)
__device__ float2 g_spec[BKC * 2 * NFFT];        // packed forward spectra, 8.4 MB
__device__ float  g_cc[BKC * PC * NFFT];         // per-pair fftshifted cc, 12.6 MB

__device__ __forceinline__ float2 cmulf(float2 a, float2 b) {
    return make_float2(a.x * b.x - a.y * b.y, a.x * b.y + a.y * b.x);
}

// Build accurate twiddle table: tw[k] = exp(-2*pi*i*k/NFFT), k in [0, NFFT/2)
__device__ __forceinline__ void build_twiddles(float2* tw) {
    for (int k = threadIdx.x; k < NFFT / 2; k += THREADS_FFT) {
        float s, c;
        sincospif(-(float)k * (1.0f / (float)HALF), &s, &c);  // angle = -pi*k/4096
        tw[k] = make_float2(c, s);
    }
}

// ---------------------------------------------------------------------------
// In-shared-memory Stockham radix-2 FFT, 8192 points, 1024 threads.
// INV=false: forward. INV=true: inverse (no 1/N scaling). Returns final buffer.
// ---------------------------------------------------------------------------
template <bool INV>
__device__ float2* block_fft(float2* b0, float2* b1, const float2* __restrict__ tw) {
    float2* src = b0;
    float2* dst = b1;
    int ls = 0;  // log2(s)
    for (int n = NFFT; n > 1; n >>= 1, ls++) {
        #pragma unroll 4
        for (int t = threadIdx.x; t < NFFT / 2; t += THREADS_FFT) {
            int p = t >> ls;
            float2 a  = src[t];
            float2 bb = src[t + NFFT / 2];
            float2 w  = tw[p << ls];
            if (INV) w.y = -w.y;
            int j = t + (p << ls);                 // q + s*2p
            dst[j] = make_float2(a.x + bb.x, a.y + bb.y);
            float2 d = make_float2(a.x - bb.x, a.y - bb.y);
            dst[j + (1 << ls)] = cmulf(d, w);
        }
        __syncthreads();
        float2* tmp = src; src = dst; dst = tmp;
    }
    return src;
}

// ---------------------------------------------------------------------------
// Kernel 1: forward FFT of packed mic pairs.
// Block g in [0,128): bk = g>>1, h = g&1 -> FFT(mic[2h] + i*mic[2h+1])
// ---------------------------------------------------------------------------
__global__ __launch_bounds__(THREADS_FFT, 1)
void fwd_fft_kernel(const float* __restrict__ signal) {
    extern __shared__ float2 sm[];
    float2* b0 = sm;
    float2* b1 = sm + NFFT;
    float2* tw = sm + 2 * NFFT;

    build_twiddles(tw);

    int g  = blockIdx.x;
    int bk = g >> 1;
    int h  = g & 1;
    const float* s0 = signal + ((size_t)bk * MC + 2 * h) * NFFT;
    const float* s1 = s0 + NFFT;

    for (int i = threadIdx.x; i < NFFT; i += THREADS_FFT)
        b0[i] = make_float2(s0[i], s1[i]);
    __syncthreads();

    float2* res = block_fft<false>(b0, b1, tw);

    float2* out = &g_spec[(size_t)g * NFFT];
    for (int i = threadIdx.x; i < NFFT; i += THREADS_FFT)
        out[i] = res[i];
}

// ---------------------------------------------------------------------------
// Kernel 2: cross-spectra + PHAT for two pairs, packed inverse FFT,
// fftshift + scale, write cc.
// Block g in [0,192): bk = g/3, pp = g%3; pairs 2pp and 2pp+1.
// Pairs (triu k=1 of 4): (0,1)(0,2)(0,3)(1,2)(1,3)(2,3)
// ---------------------------------------------------------------------------
template <int IA, int JA, int IB, int JB>
__device__ void build_phat_packed(const float2* __restrict__ Za,
                                  const float2* __restrict__ Zb,
                                  float2* __restrict__ w) {
    for (int f = threadIdx.x; f < NFFT; f += THREADS_FFT) {
        int fr = (NFFT - f) & (NFFT - 1);
        float2 za  = Za[f],  zar = Za[fr];
        float2 zb  = Zb[f],  zbr = Zb[fr];
        // Extract real-signal spectra from packed FFTs:
        // X0 = (Za + conj(ZaR))/2 ; X1 = (Za - conj(ZaR))/(2i)
        float2 X[4];
        X[0] = make_float2(0.5f * (za.x + zar.x),  0.5f * (za.y - zar.y));
        X[1] = make_float2(0.5f * (za.y + zar.y), -0.5f * (za.x - zar.x));
        X[2] = make_float2(0.5f * (zb.x + zbr.x),  0.5f * (zb.y - zbr.y));
        X[3] = make_float2(0.5f * (zb.y + zbr.y), -0.5f * (zb.x - zbr.x));

        float2 pa, pb;
        {
            float2 xi = X[IA], xj = X[JA];
            float2 c = make_float2(xi.x * xj.x + xi.y * xj.y,
                                   xi.y * xj.x - xi.x * xj.y);   // Xi * conj(Xj)
            float mag = sqrtf(c.x * c.x + c.y * c.y);
            float inv = 1.0f / fmaxf(mag, 1e-9f);
            pa = make_float2(c.x * inv, c.y * inv);
        }
        {
            float2 xi = X[IB], xj = X[JB];
            float2 c = make_float2(xi.x * xj.x + xi.y * xj.y,
                                   xi.y * xj.x - xi.x * xj.y);
            float mag = sqrtf(c.x * c.x + c.y * c.y);
            float inv = 1.0f / fmaxf(mag, 1e-9f);
            pb = make_float2(c.x * inv, c.y * inv);
        }
        // w = P_A + i * P_B  (both Hermitian -> one complex ifft gives both cc's)
        w[f] = make_float2(pa.x - pb.y, pa.y + pb.x);
    }
}

__global__ __launch_bounds__(THREADS_FFT, 1)
void cross_ifft_kernel() {
    extern __shared__ float2 sm[];
    float2* b0 = sm;
    float2* b1 = sm + NFFT;
    float2* tw = sm + 2 * NFFT;

    build_twiddles(tw);

    int g  = blockIdx.x;
    int bk = g / 3;
    int pp = g - 3 * bk;

    const float2* Za = &g_spec[(size_t)(bk * 2 + 0) * NFFT];
    const float2* Zb = &g_spec[(size_t)(bk * 2 + 1) * NFFT];

    // pp=0 -> pairs (0,1),(0,2); pp=1 -> (0,3),(1,2); pp=2 -> (1,3),(2,3)
    if      (pp == 0) build_phat_packed<0, 1, 0, 2>(Za, Zb, b0);
    else if (pp == 1) build_phat_packed<0, 3, 1, 2>(Za, Zb, b0);
    else              build_phat_packed<1, 3, 2, 3>(Za, Zb, b0);
    __syncthreads();

    float2* res = block_fft<true>(b0, b1, tw);  // un-normalized ifft

    // fftshift (index ^ 4096) + 1/N scale, write both cc rows
    const float invN = 1.0f / (float)NFFT;
    int pA = 2 * pp, pB = pA + 1;
    float* CA = &g_cc[((size_t)bk * PC + pA) * NFFT];
    float* CB = &g_cc[((size_t)bk * PC + pB) * NFFT];
    for (int idx = threadIdx.x; idx < NFFT; idx += THREADS_FFT) {
        float2 z = res[idx ^ HALF];
        CA[idx] = z.x * invN;
        CB[idx] = z.y * invN;
    }
}

// ---------------------------------------------------------------------------
// Kernel 3: SRP grid accumulation (direct 10-tap band sums).
// Block = (bk, gi); thread = gj.
// Delay path mimics XLA:CPU partial-fast-math codegen (reassoc+contract,
// honored division):
//   dist = sqrt( fma(dx, dx, dy*dy) )          [DAGCombiner fuses 1st fmul]
//   x    = (d_i - d_j) * fl(16000/343)          [InstCombine (X/C1)*C2 fold]
//   delay = roundeven(x) + N/2
// All other ops are single correctly-rounded ops (match both sides).
// ---------------------------------------------------------------------------
__global__ __launch_bounds__(GD)
void grid_kernel(const float* __restrict__ mic,
                 const float* __restrict__ room,
                 float* __restrict__ out) {
    int bid = blockIdx.x;
    int bk  = bid >> 7;          // /128
    int gi  = bid & 127;
    int b   = bk >> 2;           // /K
    int gj  = threadIdx.x;

    const float step = 1.0f / 127.0f;  // fl(1/127); matches jnp.linspace step
    float tx = __fmul_rn((float)gi, step);
    float ty = __fmul_rn((float)gj, step);
    float gx = __fmul_rn(__ldg(&room[b * 3 + 0]), tx);
    float gy = __fmul_rn(__ldg(&room[b * 3 + 1]), ty);

    float d[4];
    #pragma unroll
    for (int m = 0; m < 4; m++) {
        float mx = __ldg(&mic[((size_t)bk * MC + m) * 3 + 0]);
        float my = __ldg(&mic[((size_t)bk * MC + m) * 3 + 1]);
        float dx = __fsub_rn(gx, mx);
        float dy = __fsub_rn(gy, my);
        // LLVM contraction order: fma(dx, dx, dy*dy)
        float dy2 = __fmul_rn(dy, dy);
        d[m] = sqrtf(__fmaf_rn(dx, dx, dy2));
    }

    // combined constant fl(16000/343) — correctly rounded f32 division
    const float SCALE = __fdiv_rn(16000.0f, 343.0f);

    const int ii[PC] = {0, 0, 0, 1, 1, 2};
    const int jj[PC] = {1, 2, 3, 2, 3, 3};
    float acc = 0.0f;
    #pragma unroll
    for (int p = 0; p < PC; p++) {
        float x    = __fmul_rn(__fsub_rn(d[ii[p]], d[jj[p]]), SCALE);
        int   delay = (int)rintf(x) + HALF;                   // half-even
        const float* C = &g_cc[((size_t)bk * PC + p) * NFFT];
        int base = delay - 5;                                 // offs = -5..+4
        float v = 0.0f;
        #pragma unroll
        for (int o = 0; o < 10; o++) {
            int id = min(max(base + o, 0), NFFT - 1);
            v += __ldg(&C[id]);
        }
        acc += v;
    }
    out[(size_t)bk * (GD * GD) + gi * GD + gj] = acc;
}

// ---------------------------------------------------------------------------
// Kernel 4: per-(b,k) max-normalize in place.
// ---------------------------------------------------------------------------
__global__ __launch_bounds__(256)
void norm_kernel(float* __restrict__ out) {
    __shared__ float red[8];
    int bk = blockIdx.x;
    float* p = out + (size_t)bk * (GD * GD);

    float mx = -__int_as_float(0x7f800000);  // -inf
    for (int i = threadIdx.x; i < GD * GD; i += 256)
        mx = fmaxf(mx, p[i]);
    #pragma unroll
    for (int o = 16; o; o >>= 1)
        mx = fmaxf(mx, __shfl_xor_sync(0xffffffffu, mx, o));
    if ((threadIdx.x & 31) == 0) red[threadIdx.x >> 5] = mx;
    __syncthreads();
    if (threadIdx.x < 32) {
        float v = (threadIdx.x < 8) ? red[threadIdx.x] : -__int_as_float(0x7f800000);
        #pragma unroll
        for (int o = 4; o; o >>= 1)
            v = fmaxf(v, __shfl_xor_sync(0xffffffffu, v, o));
        if (threadIdx.x == 0) red[0] = v;
    }
    __syncthreads();
    float m = red[0];
    for (int i = threadIdx.x; i < GD * GD; i += 256)
        p[i] = __fdiv_rn(p[i], m);
}

// ---------------------------------------------------------------------------
extern "C" void kernel_launch(void* const* d_in, const int* in_sizes, int n_in,
                              void* d_out, int out_size) {
    const float* signal = (const float*)d_in[0];  // (B,K,M,N)
    const float* mic    = (const float*)d_in[1];  // (B,K,M,3)
    const float* room   = (const float*)d_in[2];  // (B,3)
    float* out = (float*)d_out;                   // (B,K,G*G)

    const int smem = (2 * NFFT + NFFT / 2) * (int)sizeof(float2);  // 160 KB
    cudaFuncSetAttribute(fwd_fft_kernel,    cudaFuncAttributeMaxDynamicSharedMemorySize, smem);
    cudaFuncSetAttribute(cross_ifft_kernel, cudaFuncAttributeMaxDynamicSharedMemorySize, smem);

    fwd_fft_kernel<<<BKC * 2, THREADS_FFT, smem>>>(signal);
    cross_ifft_kernel<<<BKC * 3, THREADS_FFT, smem>>>();
    grid_kernel<<<BKC * GD, GD>>>(mic, room, out);
    norm_kernel<<<BKC, 256>>>(out);
}

// round 5
// speedup vs baseline: 1.9207x; 1.9207x over previous
#include <cuda_runtime.h>
#include <cstdint>

// Problem constants
#define NFFT 8192
#define HALF 4096
#define GD   128
#define BC   16
#define KC   4
#define MC   4
#define PC   6
#define BKC  (BC*KC)   // 64
#define THREADS_FFT 1024

// Scratch (device globals — no allocation allowed)
__device__ float2   g_spec[BKC * 2 * NFFT];      // packed forward spectra, 8.4 MB
__device__ float    g_cc[BKC * PC * NFFT];       // per-pair fftshifted cc, 12.6 MB
__device__ unsigned g_maxenc[BKC];               // per-(b,k) max, ordered-uint encoded

__device__ __forceinline__ float2 cmulf(float2 a, float2 b) {
    return make_float2(a.x * b.x - a.y * b.y, a.x * b.y + a.y * b.x);
}
__device__ __forceinline__ float2 caddf(float2 a, float2 b) { return make_float2(a.x + b.x, a.y + b.y); }
__device__ __forceinline__ float2 csubf(float2 a, float2 b) { return make_float2(a.x - b.x, a.y - b.y); }

// ordered-uint encoding for float atomicMax (handles negatives)
__device__ __forceinline__ unsigned enc_f(float f) {
    unsigned u = __float_as_uint(f);
    return (u & 0x80000000u) ? ~u : (u | 0x80000000u);
}
__device__ __forceinline__ float dec_f(unsigned e) {
    unsigned u = (e & 0x80000000u) ? (e & 0x7fffffffu) : ~e;
    return __uint_as_float(u);
}
#define ENC_NEG_INF 0x007fffffu   // enc(-inf)

// Build accurate twiddle table: tw[k] = exp(-2*pi*i*k/NFFT), k in [0, NFFT/2)
__device__ __forceinline__ void build_twiddles(float2* tw) {
    for (int k = threadIdx.x; k < NFFT / 2; k += THREADS_FFT) {
        float s, c;
        sincospif(-(float)k * (1.0f / (float)HALF), &s, &c);  // angle = -pi*k/4096
        tw[k] = make_float2(c, s);
    }
}

// ---------------------------------------------------------------------------
// Shared-memory Stockham FFT, 8192 points, 1024 threads.
// 6 radix-4 stages (exact composition of radix-2 pairs) + 1 final radix-2.
// INV=false forward, INV=true inverse (no 1/N scale). Returns final buffer.
// ---------------------------------------------------------------------------
template <bool INV>
__device__ float2* block_fft(float2* b0, float2* b1, const float2* __restrict__ tw) {
    float2* src = b0;
    float2* dst = b1;

    // radix-4 stages: ls = 0,2,4,6,8,10  (s = 2^ls)
    #pragma unroll
    for (int ls = 0; ls <= 10; ls += 2) {
        #pragma unroll 2
        for (int u = threadIdx.x; u < NFFT / 4; u += THREADS_FFT) {
            int p = u >> ls;                        // p' in [0, N/4s)
            float2 A = src[u];
            float2 B = src[u + NFFT / 4];
            float2 C = src[u + NFFT / 2];
            float2 D = src[u + 3 * (NFFT / 4)];

            float2 S0 = caddf(A, C), S1 = caddf(B, D);
            float2 T0 = csubf(A, C), T1 = csubf(B, D);
            // forward: E1 = T0 - i*T1, E3 = T0 + i*T1   (swap for inverse)
            float2 E1, E3;
            if (!INV) {
                E1 = make_float2(T0.x + T1.y, T0.y - T1.x);
                E3 = make_float2(T0.x - T1.y, T0.y + T1.x);
            } else {
                E1 = make_float2(T0.x - T1.y, T0.y + T1.x);
                E3 = make_float2(T0.x + T1.y, T0.y - T1.x);
            }
            float2 w1 = tw[p << ls];                // W^(s*p)
            float2 w2 = tw[p << (ls + 1)];          // W^(2s*p)
            if (INV) { w1.y = -w1.y; w2.y = -w2.y; }
            float2 w3 = cmulf(w1, w2);              // W^(3s*p)

            int s = 1 << ls;
            int j = u + 3 * (p << ls);              // q + 4*s*p
            dst[j]         = caddf(S0, S1);
            dst[j + s]     = cmulf(E1, w1);
            dst[j + 2 * s] = cmulf(csubf(S0, S1), w2);
            dst[j + 3 * s] = cmulf(E3, w3);
        }
        __syncthreads();
        float2* tmp = src; src = dst; dst = tmp;
    }

    // final radix-2 stage, ls = 12: p = 0 -> twiddle = 1
    #pragma unroll 4
    for (int t = threadIdx.x; t < NFFT / 2; t += THREADS_FFT) {
        float2 a = src[t];
        float2 b = src[t + NFFT / 2];
        dst[t]            = caddf(a, b);
        dst[t + NFFT / 2] = csubf(a, b);
    }
    __syncthreads();
    return dst;
}

// ---------------------------------------------------------------------------
// Kernel 1: forward FFT of packed mic pairs.
// Block g in [0,128): bk = g>>1, h = g&1 -> FFT(mic[2h] + i*mic[2h+1])
// Block 0 also resets the per-(b,k) max accumulators.
// ---------------------------------------------------------------------------
__global__ __launch_bounds__(THREADS_FFT, 1)
void fwd_fft_kernel(const float* __restrict__ signal) {
    extern __shared__ float2 sm[];
    float2* b0 = sm;
    float2* b1 = sm + NFFT;
    float2* tw = sm + 2 * NFFT;

    if (blockIdx.x == 0 && threadIdx.x < BKC)
        g_maxenc[threadIdx.x] = ENC_NEG_INF;

    build_twiddles(tw);

    int g  = blockIdx.x;
    int bk = g >> 1;
    int h  = g & 1;
    const float* s0 = signal + ((size_t)bk * MC + 2 * h) * NFFT;
    const float* s1 = s0 + NFFT;

    for (int i = threadIdx.x; i < NFFT; i += THREADS_FFT)
        b0[i] = make_float2(s0[i], s1[i]);
    __syncthreads();

    float2* res = block_fft<false>(b0, b1, tw);

    float2* out = &g_spec[(size_t)g * NFFT];
    for (int i = threadIdx.x; i < NFFT; i += THREADS_FFT)
        out[i] = res[i];
}

// ---------------------------------------------------------------------------
// Kernel 2: cross-spectra + PHAT for two pairs, packed inverse FFT,
// fftshift + scale, write cc.
// Block g in [0,192): bk = g/3, pp = g%3; pairs 2pp and 2pp+1.
// ---------------------------------------------------------------------------
template <int IA, int JA, int IB, int JB>
__device__ void build_phat_packed(const float2* __restrict__ Za,
                                  const float2* __restrict__ Zb,
                                  float2* __restrict__ w) {
    for (int f = threadIdx.x; f < NFFT; f += THREADS_FFT) {
        int fr = (NFFT - f) & (NFFT - 1);
        float2 za  = Za[f],  zar = Za[fr];
        float2 zb  = Zb[f],  zbr = Zb[fr];
        // X0 = (Za + conj(ZaR))/2 ; X1 = (Za - conj(ZaR))/(2i)
        float2 X[4];
        X[0] = make_float2(0.5f * (za.x + zar.x),  0.5f * (za.y - zar.y));
        X[1] = make_float2(0.5f * (za.y + zar.y), -0.5f * (za.x - zar.x));
        X[2] = make_float2(0.5f * (zb.x + zbr.x),  0.5f * (zb.y - zbr.y));
        X[3] = make_float2(0.5f * (zb.y + zbr.y), -0.5f * (zb.x - zbr.x));

        float2 pa, pb;
        {
            float2 xi = X[IA], xj = X[JA];
            float2 c = make_float2(xi.x * xj.x + xi.y * xj.y,
                                   xi.y * xj.x - xi.x * xj.y);   // Xi * conj(Xj)
            float mag = sqrtf(c.x * c.x + c.y * c.y);
            float inv = 1.0f / fmaxf(mag, 1e-9f);
            pa = make_float2(c.x * inv, c.y * inv);
        }
        {
            float2 xi = X[IB], xj = X[JB];
            float2 c = make_float2(xi.x * xj.x + xi.y * xj.y,
                                   xi.y * xj.x - xi.x * xj.y);
            float mag = sqrtf(c.x * c.x + c.y * c.y);
            float inv = 1.0f / fmaxf(mag, 1e-9f);
            pb = make_float2(c.x * inv, c.y * inv);
        }
        // w = P_A + i * P_B  (both Hermitian -> one complex ifft gives both cc's)
        w[f] = make_float2(pa.x - pb.y, pa.y + pb.x);
    }
}

__global__ __launch_bounds__(THREADS_FFT, 1)
void cross_ifft_kernel() {
    extern __shared__ float2 sm[];
    float2* b0 = sm;
    float2* b1 = sm + NFFT;
    float2* tw = sm + 2 * NFFT;

    build_twiddles(tw);

    int g  = blockIdx.x;
    int bk = g / 3;
    int pp = g - 3 * bk;

    const float2* Za = &g_spec[(size_t)(bk * 2 + 0) * NFFT];
    const float2* Zb = &g_spec[(size_t)(bk * 2 + 1) * NFFT];

    // pp=0 -> pairs (0,1),(0,2); pp=1 -> (0,3),(1,2); pp=2 -> (1,3),(2,3)
    if      (pp == 0) build_phat_packed<0, 1, 0, 2>(Za, Zb, b0);
    else if (pp == 1) build_phat_packed<0, 3, 1, 2>(Za, Zb, b0);
    else              build_phat_packed<1, 3, 2, 3>(Za, Zb, b0);
    __syncthreads();

    float2* res = block_fft<true>(b0, b1, tw);  // un-normalized ifft

    // fftshift (index ^ 4096) + 1/N scale, write both cc rows
    const float invN = 1.0f / (float)NFFT;
    int pA = 2 * pp, pB = pA + 1;
    float* CA = &g_cc[((size_t)bk * PC + pA) * NFFT];
    float* CB = &g_cc[((size_t)bk * PC + pB) * NFFT];
    for (int idx = threadIdx.x; idx < NFFT; idx += THREADS_FFT) {
        float2 z = res[idx ^ HALF];
        CA[idx] = z.x * invN;
        CB[idx] = z.y * invN;
    }
}

// ---------------------------------------------------------------------------
// Kernel 3: SRP grid accumulation + per-(b,k) max via atomicMax.
// Block = (bk, gi); thread = gj.
// Delay path mimics XLA:CPU partial-fast-math codegen — DO NOT CHANGE:
//   dist = sqrt( fma(dx, dx, dy*dy) )
//   x    = (d_i - d_j) * fl(16000/343)
//   delay = roundeven(x) + N/2
// ---------------------------------------------------------------------------
__global__ __launch_bounds__(GD)
void grid_kernel(const float* __restrict__ mic,
                 const float* __restrict__ room,
                 float* __restrict__ out) {
    __shared__ float wred[4];
    int bid = blockIdx.x;
    int bk  = bid >> 7;          // /128
    int gi  = bid & 127;
    int b   = bk >> 2;           // /K
    int gj  = threadIdx.x;

    const float step = 1.0f / 127.0f;  // fl(1/127); matches jnp.linspace step
    float tx = __fmul_rn((float)gi, step);
    float ty = __fmul_rn((float)gj, step);
    float gx = __fmul_rn(__ldg(&room[b * 3 + 0]), tx);
    float gy = __fmul_rn(__ldg(&room[b * 3 + 1]), ty);

    float d[4];
    #pragma unroll
    for (int m = 0; m < 4; m++) {
        float mx = __ldg(&mic[((size_t)bk * MC + m) * 3 + 0]);
        float my = __ldg(&mic[((size_t)bk * MC + m) * 3 + 1]);
        float dx = __fsub_rn(gx, mx);
        float dy = __fsub_rn(gy, my);
        float dy2 = __fmul_rn(dy, dy);
        d[m] = sqrtf(__fmaf_rn(dx, dx, dy2));   // LLVM contraction order
    }

    const float SCALE = __fdiv_rn(16000.0f, 343.0f);  // fl(16000/343)

    const int ii[PC] = {0, 0, 0, 1, 1, 2};
    const int jj[PC] = {1, 2, 3, 2, 3, 3};
    float acc = 0.0f;
    #pragma unroll
    for (int p = 0; p < PC; p++) {
        float x     = __fmul_rn(__fsub_rn(d[ii[p]], d[jj[p]]), SCALE);
        int   delay = (int)rintf(x) + HALF;                   // half-even
        const float* C = &g_cc[((size_t)bk * PC + p) * NFFT];
        int base = delay - 5;                                 // offs = -5..+4
        float v = 0.0f;
        #pragma unroll
        for (int o = 0; o < 10; o++) {
            int id = min(max(base + o, 0), NFFT - 1);
            v += __ldg(&C[id]);
        }
        acc += v;
    }
    out[(size_t)bk * (GD * GD) + gi * GD + gj] = acc;

    // block max -> atomicMax (ordered-uint; max is order-independent -> deterministic)
    float mx = acc;
    #pragma unroll
    for (int o = 16; o; o >>= 1)
        mx = fmaxf(mx, __shfl_xor_sync(0xffffffffu, mx, o));
    if ((threadIdx.x & 31) == 0) wred[threadIdx.x >> 5] = mx;
    __syncthreads();
    if (threadIdx.x == 0) {
        mx = fmaxf(fmaxf(wred[0], wred[1]), fmaxf(wred[2], wred[3]));
        atomicMax(&g_maxenc[bk], enc_f(mx));
    }
}

// ---------------------------------------------------------------------------
// Kernel 4: wide vectorized divide by per-(b,k) max.
// 1024 blocks x 256 threads, one float4 per thread.
// ---------------------------------------------------------------------------
__global__ __launch_bounds__(256)
void divide_kernel(float* __restrict__ out) {
    int i  = blockIdx.x * 256 + threadIdx.x;   // float4 index, [0, 256K)
    int bk = i >> 12;                          // 4096 float4 per (b,k)
    float m = dec_f(g_maxenc[bk]);
    float4 v = reinterpret_cast<float4*>(out)[i];
    v.x = __fdiv_rn(v.x, m);
    v.y = __fdiv_rn(v.y, m);
    v.z = __fdiv_rn(v.z, m);
    v.w = __fdiv_rn(v.w, m);
    reinterpret_cast<float4*>(out)[i] = v;
}

// ---------------------------------------------------------------------------
extern "C" void kernel_launch(void* const* d_in, const int* in_sizes, int n_in,
                              void* d_out, int out_size) {
    const float* signal = (const float*)d_in[0];  // (B,K,M,N)
    const float* mic    = (const float*)d_in[1];  // (B,K,M,3)
    const float* room   = (const float*)d_in[2];  // (B,3)
    float* out = (float*)d_out;                   // (B,K,G*G)

    const int smem = (2 * NFFT + NFFT / 2) * (int)sizeof(float2);  // 160 KB
    cudaFuncSetAttribute(fwd_fft_kernel,    cudaFuncAttributeMaxDynamicSharedMemorySize, smem);
    cudaFuncSetAttribute(cross_ifft_kernel, cudaFuncAttributeMaxDynamicSharedMemorySize, smem);

    fwd_fft_kernel<<<BKC * 2, THREADS_FFT, smem>>>(signal);
    cross_ifft_kernel<<<BKC * 3, THREADS_FFT, smem>>>();
    grid_kernel<<<BKC * GD, GD>>>(mic, room, out);
    divide_kernel<<<(BKC * GD * GD / 4) / 256, 256>>>(out);
}

// round 6
// speedup vs baseline: 1.9403x; 1.0102x over previous
#include <cuda_runtime.h>
#include <cstdint>

// Problem constants
#define NFFT 8192
#define HALF 4096
#define GD   128
#define BC   16
#define KC   4
#define MC   4
#define PC   6
#define BKC  (BC*KC)   // 64
#define THREADS_FFT 1024

// Bank-conflict-killing smem swizzle: XOR addr bits 4-5 into bits {0,2} / {1,3}.
// phi(i) = i ^ (((i>>4)&3) * 5). Linear over GF(2); bijective on [0, NFFT).
#define IX(i) ((i) ^ ((((i) >> 4) & 3) * 5))

// Scratch (device globals — no allocation allowed)
__device__ float2   g_spec[BKC * 2 * NFFT];      // packed forward spectra, 8.4 MB
__device__ float    g_cc[BKC * PC * NFFT];       // per-pair fftshifted cc, 12.6 MB
__device__ unsigned g_maxenc[BKC];               // per-(b,k) max, ordered-uint encoded

__device__ __forceinline__ float2 cmulf(float2 a, float2 b) {
    return make_float2(a.x * b.x - a.y * b.y, a.x * b.y + a.y * b.x);
}
__device__ __forceinline__ float2 caddf(float2 a, float2 b) { return make_float2(a.x + b.x, a.y + b.y); }
__device__ __forceinline__ float2 csubf(float2 a, float2 b) { return make_float2(a.x - b.x, a.y - b.y); }

// ordered-uint encoding for float atomicMax (handles negatives)
__device__ __forceinline__ unsigned enc_f(float f) {
    unsigned u = __float_as_uint(f);
    return (u & 0x80000000u) ? ~u : (u | 0x80000000u);
}
__device__ __forceinline__ float dec_f(unsigned e) {
    unsigned u = (e & 0x80000000u) ? (e & 0x7fffffffu) : ~e;
    return __uint_as_float(u);
}
#define ENC_NEG_INF 0x007fffffu   // enc(-inf)

// Build accurate twiddle table: tw[k] = exp(-2*pi*i*k/NFFT), k in [0, NFFT/2)
__device__ __forceinline__ void build_twiddles(float2* tw) {
    for (int k = threadIdx.x; k < NFFT / 2; k += THREADS_FFT) {
        float s, c;
        sincospif(-(float)k * (1.0f / (float)HALF), &s, &c);  // angle = -pi*k/4096
        tw[k] = make_float2(c, s);
    }
}

// ---------------------------------------------------------------------------
// Shared-memory Stockham FFT, 8192 points, 1024 threads.
// 6 radix-4 stages + 1 final radix-2. All smem accesses via IX() swizzle.
// Only w1 is loaded from the table (broadcast pattern); w2 = w1^2, w3 = w1*w2.
// INV=false forward, INV=true inverse (no 1/N scale). Returns final buffer.
// ---------------------------------------------------------------------------
template <bool INV>
__device__ float2* block_fft(float2* b0, float2* b1, const float2* __restrict__ tw) {
    float2* src = b0;
    float2* dst = b1;

    // radix-4 stages: ls = 0,2,4,6,8,10  (s = 2^ls)
    #pragma unroll
    for (int ls = 0; ls <= 10; ls += 2) {
        #pragma unroll 2
        for (int u = threadIdx.x; u < NFFT / 4; u += THREADS_FFT) {
            int p = u >> ls;                        // p' in [0, N/4s)
            float2 A = src[IX(u)];
            float2 B = src[IX(u + NFFT / 4)];
            float2 C = src[IX(u + NFFT / 2)];
            float2 D = src[IX(u + 3 * (NFFT / 4))];

            float2 S0 = caddf(A, C), S1 = caddf(B, D);
            float2 T0 = csubf(A, C), T1 = csubf(B, D);
            // forward: E1 = T0 - i*T1, E3 = T0 + i*T1   (swap for inverse)
            float2 E1, E3;
            if (!INV) {
                E1 = make_float2(T0.x + T1.y, T0.y - T1.x);
                E3 = make_float2(T0.x - T1.y, T0.y + T1.x);
            } else {
                E1 = make_float2(T0.x - T1.y, T0.y + T1.x);
                E3 = make_float2(T0.x + T1.y, T0.y - T1.x);
            }
            float2 w1 = tw[p << ls];                // W^(s*p)  (broadcast within groups)
            if (INV) w1.y = -w1.y;
            float2 w2 = cmulf(w1, w1);              // W^(2s*p)
            float2 w3 = cmulf(w1, w2);              // W^(3s*p)

            int s = 1 << ls;
            int j = u + 3 * (p << ls);              // q + 4*s*p
            dst[IX(j)]         = caddf(S0, S1);
            dst[IX(j + s)]     = cmulf(E1, w1);
            dst[IX(j + 2 * s)] = cmulf(csubf(S0, S1), w2);
            dst[IX(j + 3 * s)] = cmulf(E3, w3);
        }
        __syncthreads();
        float2* tmp = src; src = dst; dst = tmp;
    }

    // final radix-2 stage, ls = 12: p = 0 -> twiddle = 1
    #pragma unroll 4
    for (int t = threadIdx.x; t < NFFT / 2; t += THREADS_FFT) {
        float2 a = src[IX(t)];
        float2 b = src[IX(t + NFFT / 2)];
        dst[IX(t)]            = caddf(a, b);
        dst[IX(t + NFFT / 2)] = csubf(a, b);
    }
    __syncthreads();
    return dst;
}

// ---------------------------------------------------------------------------
// Kernel 1: forward FFT of packed mic pairs.
// Block g in [0,128): bk = g>>1, h = g&1 -> FFT(mic[2h] + i*mic[2h+1])
// Block 0 also resets the per-(b,k) max accumulators.
// ---------------------------------------------------------------------------
__global__ __launch_bounds__(THREADS_FFT, 1)
void fwd_fft_kernel(const float* __restrict__ signal) {
    extern __shared__ float2 sm[];
    float2* b0 = sm;
    float2* b1 = sm + NFFT;
    float2* tw = sm + 2 * NFFT;

    if (blockIdx.x == 0 && threadIdx.x < BKC)
        g_maxenc[threadIdx.x] = ENC_NEG_INF;

    build_twiddles(tw);

    int g  = blockIdx.x;
    int bk = g >> 1;
    int h  = g & 1;
    const float* s0 = signal + ((size_t)bk * MC + 2 * h) * NFFT;
    const float* s1 = s0 + NFFT;

    for (int i = threadIdx.x; i < NFFT; i += THREADS_FFT)
        b0[IX(i)] = make_float2(s0[i], s1[i]);
    __syncthreads();

    float2* res = block_fft<false>(b0, b1, tw);

    float2* out = &g_spec[(size_t)g * NFFT];
    for (int i = threadIdx.x; i < NFFT; i += THREADS_FFT)
        out[i] = res[IX(i)];
}

// ---------------------------------------------------------------------------
// Kernel 2: cross-spectra + PHAT for two pairs, packed inverse FFT,
// fftshift + scale, write cc.
// Block g in [0,192): bk = g/3, pp = g%3; pairs 2pp and 2pp+1.
// ---------------------------------------------------------------------------
template <int IA, int JA, int IB, int JB>
__device__ void build_phat_packed(const float2* __restrict__ Za,
                                  const float2* __restrict__ Zb,
                                  float2* __restrict__ w) {
    for (int f = threadIdx.x; f < NFFT; f += THREADS_FFT) {
        int fr = (NFFT - f) & (NFFT - 1);
        float2 za  = Za[f],  zar = Za[fr];
        float2 zb  = Zb[f],  zbr = Zb[fr];
        // X0 = (Za + conj(ZaR))/2 ; X1 = (Za - conj(ZaR))/(2i)
        float2 X[4];
        X[0] = make_float2(0.5f * (za.x + zar.x),  0.5f * (za.y - zar.y));
        X[1] = make_float2(0.5f * (za.y + zar.y), -0.5f * (za.x - zar.x));
        X[2] = make_float2(0.5f * (zb.x + zbr.x),  0.5f * (zb.y - zbr.y));
        X[3] = make_float2(0.5f * (zb.y + zbr.y), -0.5f * (zb.x - zbr.x));

        float2 pa, pb;
        {
            float2 xi = X[IA], xj = X[JA];
            float2 c = make_float2(xi.x * xj.x + xi.y * xj.y,
                                   xi.y * xj.x - xi.x * xj.y);   // Xi * conj(Xj)
            float mag = sqrtf(c.x * c.x + c.y * c.y);
            float inv = 1.0f / fmaxf(mag, 1e-9f);
            pa = make_float2(c.x * inv, c.y * inv);
        }
        {
            float2 xi = X[IB], xj = X[JB];
            float2 c = make_float2(xi.x * xj.x + xi.y * xj.y,
                                   xi.y * xj.x - xi.x * xj.y);
            float mag = sqrtf(c.x * c.x + c.y * c.y);
            float inv = 1.0f / fmaxf(mag, 1e-9f);
            pb = make_float2(c.x * inv, c.y * inv);
        }
        // w = P_A + i * P_B  (both Hermitian -> one complex ifft gives both cc's)
        w[IX(f)] = make_float2(pa.x - pb.y, pa.y + pb.x);
    }
}

__global__ __launch_bounds__(THREADS_FFT, 1)
void cross_ifft_kernel() {
    extern __shared__ float2 sm[];
    float2* b0 = sm;
    float2* b1 = sm + NFFT;
    float2* tw = sm + 2 * NFFT;

    build_twiddles(tw);

    int g  = blockIdx.x;
    int bk = g / 3;
    int pp = g - 3 * bk;

    const float2* Za = &g_spec[(size_t)(bk * 2 + 0) * NFFT];
    const float2* Zb = &g_spec[(size_t)(bk * 2 + 1) * NFFT];

    // pp=0 -> pairs (0,1),(0,2); pp=1 -> (0,3),(1,2); pp=2 -> (1,3),(2,3)
    if      (pp == 0) build_phat_packed<0, 1, 0, 2>(Za, Zb, b0);
    else if (pp == 1) build_phat_packed<0, 3, 1, 2>(Za, Zb, b0);
    else              build_phat_packed<1, 3, 2, 3>(Za, Zb, b0);
    __syncthreads();

    float2* res = block_fft<true>(b0, b1, tw);  // un-normalized ifft

    // fftshift (index ^ 4096) + 1/N scale, write both cc rows
    const float invN = 1.0f / (float)NFFT;
    int pA = 2 * pp, pB = pA + 1;
    float* CA = &g_cc[((size_t)bk * PC + pA) * NFFT];
    float* CB = &g_cc[((size_t)bk * PC + pB) * NFFT];
    for (int idx = threadIdx.x; idx < NFFT; idx += THREADS_FFT) {
        float2 z = res[IX(idx ^ HALF)];
        CA[idx] = z.x * invN;
        CB[idx] = z.y * invN;
    }
}

// ---------------------------------------------------------------------------
// Kernel 3: SRP grid accumulation + per-(b,k) max via atomicMax.
// Block = (bk, gi); thread = gj.
// Delay path mimics XLA:CPU partial-fast-math codegen — DO NOT CHANGE:
//   dist = sqrt( fma(dx, dx, dy*dy) )
//   x    = (d_i - d_j) * fl(16000/343)
//   delay = roundeven(x) + N/2
// ---------------------------------------------------------------------------
__global__ __launch_bounds__(GD)
void grid_kernel(const float* __restrict__ mic,
                 const float* __restrict__ room,
                 float* __restrict__ out) {
    __shared__ float wred[4];
    int bid = blockIdx.x;
    int bk  = bid >> 7;          // /128
    int gi  = bid & 127;
    int b   = bk >> 2;           // /K
    int gj  = threadIdx.x;

    const float step = 1.0f / 127.0f;  // fl(1/127); matches jnp.linspace step
    float tx = __fmul_rn((float)gi, step);
    float ty = __fmul_rn((float)gj, step);
    float gx = __fmul_rn(__ldg(&room[b * 3 + 0]), tx);
    float gy = __fmul_rn(__ldg(&room[b * 3 + 1]), ty);

    float d[4];
    #pragma unroll
    for (int m = 0; m < 4; m++) {
        float mx = __ldg(&mic[((size_t)bk * MC + m) * 3 + 0]);
        float my = __ldg(&mic[((size_t)bk * MC + m) * 3 + 1]);
        float dx = __fsub_rn(gx, mx);
        float dy = __fsub_rn(gy, my);
        float dy2 = __fmul_rn(dy, dy);
        d[m] = sqrtf(__fmaf_rn(dx, dx, dy2));   // LLVM contraction order
    }

    const float SCALE = __fdiv_rn(16000.0f, 343.0f);  // fl(16000/343)

    const int ii[PC] = {0, 0, 0, 1, 1, 2};
    const int jj[PC] = {1, 2, 3, 2, 3, 3};
    float acc = 0.0f;
    #pragma unroll
    for (int p = 0; p < PC; p++) {
        float x     = __fmul_rn(__fsub_rn(d[ii[p]], d[jj[p]]), SCALE);
        int   delay = (int)rintf(x) + HALF;                   // half-even
        const float* C = &g_cc[((size_t)bk * PC + p) * NFFT];
        int base = delay - 5;                                 // offs = -5..+4
        float v = 0.0f;
        #pragma unroll
        for (int o = 0; o < 10; o++) {
            int id = min(max(base + o, 0), NFFT - 1);
            v += __ldg(&C[id]);
        }
        acc += v;
    }
    out[(size_t)bk * (GD * GD) + gi * GD + gj] = acc;

    // block max -> atomicMax (ordered-uint; max is order-independent -> deterministic)
    float mx = acc;
    #pragma unroll
    for (int o = 16; o; o >>= 1)
        mx = fmaxf(mx, __shfl_xor_sync(0xffffffffu, mx, o));
    if ((threadIdx.x & 31) == 0) wred[threadIdx.x >> 5] = mx;
    __syncthreads();
    if (threadIdx.x == 0) {
        mx = fmaxf(fmaxf(wred[0], wred[1]), fmaxf(wred[2], wred[3]));
        atomicMax(&g_maxenc[bk], enc_f(mx));
    }
}

// ---------------------------------------------------------------------------
// Kernel 4: wide vectorized divide by per-(b,k) max.
// 256 blocks x 256 threads, four float4 per thread (MLP=4).
// 1024 float4 per block -> 4 blocks per bk, no bk crossing.
// ---------------------------------------------------------------------------
__global__ __launch_bounds__(256)
void divide_kernel(float* __restrict__ out) {
    int bk = blockIdx.x >> 2;                  // 4 blocks per (b,k)
    float m = dec_f(g_maxenc[bk]);
    float4* o4 = reinterpret_cast<float4*>(out);
    int base = blockIdx.x * 1024 + threadIdx.x * 4;
    float4 v0 = o4[base + 0];
    float4 v1 = o4[base + 1];
    float4 v2 = o4[base + 2];
    float4 v3 = o4[base + 3];
    v0.x = __fdiv_rn(v0.x, m); v0.y = __fdiv_rn(v0.y, m);
    v0.z = __fdiv_rn(v0.z, m); v0.w = __fdiv_rn(v0.w, m);
    v1.x = __fdiv_rn(v1.x, m); v1.y = __fdiv_rn(v1.y, m);
    v1.z = __fdiv_rn(v1.z, m); v1.w = __fdiv_rn(v1.w, m);
    v2.x = __fdiv_rn(v2.x, m); v2.y = __fdiv_rn(v2.y, m);
    v2.z = __fdiv_rn(v2.z, m); v2.w = __fdiv_rn(v2.w, m);
    v3.x = __fdiv_rn(v3.x, m); v3.y = __fdiv_rn(v3.y, m);
    v3.z = __fdiv_rn(v3.z, m); v3.w = __fdiv_rn(v3.w, m);
    o4[base + 0] = v0;
    o4[base + 1] = v1;
    o4[base + 2] = v2;
    o4[base + 3] = v3;
}

// ---------------------------------------------------------------------------
extern "C" void kernel_launch(void* const* d_in, const int* in_sizes, int n_in,
                              void* d_out, int out_size) {
    const float* signal = (const float*)d_in[0];  // (B,K,M,N)
    const float* mic    = (const float*)d_in[1];  // (B,K,M,3)
    const float* room   = (const float*)d_in[2];  // (B,3)
    float* out = (float*)d_out;                   // (B,K,G*G)

    const int smem = (2 * NFFT + NFFT / 2) * (int)sizeof(float2);  // 160 KB
    cudaFuncSetAttribute(fwd_fft_kernel,    cudaFuncAttributeMaxDynamicSharedMemorySize, smem);
    cudaFuncSetAttribute(cross_ifft_kernel, cudaFuncAttributeMaxDynamicSharedMemorySize, smem);

    fwd_fft_kernel<<<BKC * 2, THREADS_FFT, smem>>>(signal);
    cross_ifft_kernel<<<BKC * 3, THREADS_FFT, smem>>>();
    grid_kernel<<<BKC * GD, GD>>>(mic, room, out);
    divide_kernel<<<256, 256>>>(out);
}